// round 9
// baseline (speedup 1.0000x reference)
#include <cuda_runtime.h>
#include <cuda_bf16.h>

// Shapes: query (N,T,C,L)=(32,64,256,64) fp32; key (T,N,C); out (T,N,C)
#define N_ 32
#define T_ 64
#define C_ 256
#define L_ 64
#define CH 4                        // n per chunk
#define NCH (N_ / CH)               // 8 chunks

__device__ float g_part[N_ * T_ * L_];
__device__ float g_probs[N_ * L_];

// ---------------------------------------------------------------------------
// scores for one chunk: 256 blocks (4 n x 64 t). R6 proven body.
// ---------------------------------------------------------------------------
__global__ __launch_bounds__(256) void k_scores_c(const float* __restrict__ q,
                                                  const float* __restrict__ key,
                                                  int chunk) {
    const int n = chunk * CH + (blockIdx.x >> 6);
    const int t = blockIdx.x & 63;
    const size_t b = (size_t)n * T_ + t;
    const int w = threadIdx.x >> 5;
    const int lane = threadIdx.x & 31;
    const int half = lane >> 4;
    const int l4 = lane & 15;

    const float kreg = key[((size_t)t * N_ + n) * C_ + (w << 5) + lane];
    const float4* __restrict__ qb = reinterpret_cast<const float4*>(q);
    const size_t rowbase = b * C_;

    float4 acc = make_float4(0.f, 0.f, 0.f, 0.f);
    #pragma unroll
    for (int i = 0; i < 16; ++i) {
        const int r = (i << 1) + half;
        const float kv = __shfl_sync(0xffffffffu, kreg, r);
        const float4 qv = qb[(rowbase + (w << 5) + r) * 16 + l4];
        acc.x = fmaf(kv, qv.x, acc.x);
        acc.y = fmaf(kv, qv.y, acc.y);
        acc.z = fmaf(kv, qv.z, acc.z);
        acc.w = fmaf(kv, qv.w, acc.w);
    }
    acc.x += __shfl_xor_sync(0xffffffffu, acc.x, 16);
    acc.y += __shfl_xor_sync(0xffffffffu, acc.y, 16);
    acc.z += __shfl_xor_sync(0xffffffffu, acc.z, 16);
    acc.w += __shfl_xor_sync(0xffffffffu, acc.w, 16);

    __shared__ float4 sm[8][16];
    if (half == 0) sm[w][l4] = acc;
    __syncthreads();
    if (threadIdx.x < 16) {
        float4 tot = sm[0][threadIdx.x];
        #pragma unroll
        for (int j = 1; j < 8; ++j) {
            const float4 v = sm[j][threadIdx.x];
            tot.x += v.x; tot.y += v.y; tot.z += v.z; tot.w += v.w;
        }
        reinterpret_cast<float4*>(g_part + b * L_)[threadIdx.x] = tot;
    }
}

// ---------------------------------------------------------------------------
// softmax for one chunk: CH blocks x 64 threads.
// ---------------------------------------------------------------------------
__global__ __launch_bounds__(64) void k_softmax_c(int chunk) {
    const int n = chunk * CH + blockIdx.x;
    const int l = threadIdx.x;
    const int w = l >> 5;
    const int lane = l & 31;

    float s = 0.f;
    const float* __restrict__ p = g_part + (size_t)n * T_ * L_ + l;
    #pragma unroll
    for (int t = 0; t < T_; ++t) s += p[(size_t)t * L_];

    float m = s;
    #pragma unroll
    for (int off = 16; off; off >>= 1)
        m = fmaxf(m, __shfl_xor_sync(0xffffffffu, m, off));
    __shared__ float wm[2];
    if (lane == 0) wm[w] = m;
    __syncthreads();
    m = fmaxf(wm[0], wm[1]);

    const float e = __expf(s - m);
    float sum = e;
    #pragma unroll
    for (int off = 16; off; off >>= 1)
        sum += __shfl_xor_sync(0xffffffffu, sum, off);
    __shared__ float ws[2];
    if (lane == 0) ws[w] = sum;
    __syncthreads();

    g_probs[n * L_ + l] = e / (ws[0] + ws[1]);
}

// ---------------------------------------------------------------------------
// out for one chunk: 256 blocks. Chunk was just streamed by scores -> L2-hot.
// ---------------------------------------------------------------------------
__global__ __launch_bounds__(256) void k_out_c(const float* __restrict__ q,
                                               float* __restrict__ out,
                                               int chunk) {
    const int n = chunk * CH + (blockIdx.x >> 6);
    const int t = blockIdx.x & 63;
    const size_t b = (size_t)n * T_ + t;
    const int w = threadIdx.x >> 5;
    const int lane = threadIdx.x & 31;
    const int half = lane >> 4;
    const int l4 = lane & 15;

    const float4 pv = reinterpret_cast<const float4*>(g_probs + n * L_)[l4];
    const float4* __restrict__ qb = reinterpret_cast<const float4*>(q);
    const size_t rowbase = b * C_;
    float* __restrict__ ob = out + ((size_t)t * N_ + n) * C_;

    #pragma unroll 8
    for (int i = 0; i < 16; ++i) {
        const int c = (w << 5) + (i << 1) + half;
        const float4 qv = qb[(rowbase + c) * 16 + l4];
        float v = fmaf(qv.x, pv.x, fmaf(qv.y, pv.y, fmaf(qv.z, pv.z, qv.w * pv.w)));
        #pragma unroll
        for (int off = 8; off; off >>= 1)
            v += __shfl_xor_sync(0xffffffffu, v, off);
        if (l4 == 0) ob[c] = v;
    }
}

// ---------------------------------------------------------------------------
// Host: multi-stream fork/join pipeline, graph-capturable.
//   stream 0 (capture): even scores+softmax chunks
//   sB:                 odd  scores+softmax chunks  (overlaps drains of 0)
//   sD:                 out chunks, each gated on its softmax's event
// Streams/events created lazily on the first (non-capture) call.
// ---------------------------------------------------------------------------
static cudaStream_t sB = 0, sD = 0;
static cudaEvent_t evF = 0, evJB = 0, evJD = 0, evC[NCH];
static int g_inited = 0;

extern "C" void kernel_launch(void* const* d_in, const int* in_sizes, int n_in,
                              void* d_out, int out_size) {
    const float* q   = (const float*)d_in[0];
    const float* key = (const float*)d_in[1];
    float* out = (float*)d_out;

    if (!g_inited) {
        cudaStreamCreateWithFlags(&sB, cudaStreamNonBlocking);
        cudaStreamCreateWithFlags(&sD, cudaStreamNonBlocking);
        cudaEventCreateWithFlags(&evF,  cudaEventDisableTiming);
        cudaEventCreateWithFlags(&evJB, cudaEventDisableTiming);
        cudaEventCreateWithFlags(&evJD, cudaEventDisableTiming);
        for (int k = 0; k < NCH; ++k)
            cudaEventCreateWithFlags(&evC[k], cudaEventDisableTiming);
        g_inited = 1;
    }

    // fork side streams off the capture stream (stream 0)
    cudaEventRecord(evF, 0);
    cudaStreamWaitEvent(sB, evF, 0);
    cudaStreamWaitEvent(sD, evF, 0);

    for (int k = 0; k < NCH; ++k) {
        cudaStream_t sk = (k & 1) ? sB : (cudaStream_t)0;
        k_scores_c<<<CH * T_, 256, 0, sk>>>(q, key, k);
        k_softmax_c<<<CH, 64, 0, sk>>>(k);
        cudaEventRecord(evC[k], sk);
        cudaStreamWaitEvent(sD, evC[k], 0);
        k_out_c<<<CH * T_, 256, 0, sD>>>(q, out, k);
    }

    // join everything back into the capture stream
    cudaEventRecord(evJB, sB);
    cudaStreamWaitEvent(0, evJB, 0);
    cudaEventRecord(evJD, sD);
    cudaStreamWaitEvent(0, evJD, 0);
}

// round 10
// speedup vs baseline: 1.0207x; 1.0207x over previous
#include <cuda_runtime.h>
#include <cuda_bf16.h>

// Shapes: query (N,T,C,L)=(32,64,256,64) fp32; key (T,N,C); out (T,N,C)
#define N_ 32
#define T_ 64
#define C_ 256
#define L_ 64
#define HN 16                        // n per chunk (2 chunks)
#define HB (HN * T_)                 // 1024 blocks per chunk phase

__device__ float g_part[N_ * T_ * L_];
__device__ float g_probs[N_ * L_];

// ---------------------------------------------------------------------------
// scores for one 16-n chunk: 1024 blocks. R6 proven body (saturates DRAM).
// ---------------------------------------------------------------------------
__global__ __launch_bounds__(256) void k_scores_h(const float* __restrict__ q,
                                                  const float* __restrict__ key,
                                                  int chunk) {
    const int n = chunk * HN + (blockIdx.x >> 6);
    const int t = blockIdx.x & 63;
    const size_t b = (size_t)n * T_ + t;
    const int w = threadIdx.x >> 5;
    const int lane = threadIdx.x & 31;
    const int half = lane >> 4;
    const int l4 = lane & 15;

    const float kreg = key[((size_t)t * N_ + n) * C_ + (w << 5) + lane];
    const float4* __restrict__ qb = reinterpret_cast<const float4*>(q);
    const size_t rowbase = b * C_;

    float4 acc = make_float4(0.f, 0.f, 0.f, 0.f);
    #pragma unroll
    for (int i = 0; i < 16; ++i) {
        const int r = (i << 1) + half;
        const float kv = __shfl_sync(0xffffffffu, kreg, r);
        const float4 qv = qb[(rowbase + (w << 5) + r) * 16 + l4];
        acc.x = fmaf(kv, qv.x, acc.x);
        acc.y = fmaf(kv, qv.y, acc.y);
        acc.z = fmaf(kv, qv.z, acc.z);
        acc.w = fmaf(kv, qv.w, acc.w);
    }
    acc.x += __shfl_xor_sync(0xffffffffu, acc.x, 16);
    acc.y += __shfl_xor_sync(0xffffffffu, acc.y, 16);
    acc.z += __shfl_xor_sync(0xffffffffu, acc.z, 16);
    acc.w += __shfl_xor_sync(0xffffffffu, acc.w, 16);

    __shared__ float4 sm[8][16];
    if (half == 0) sm[w][l4] = acc;
    __syncthreads();
    if (threadIdx.x < 16) {
        float4 tot = sm[0][threadIdx.x];
        #pragma unroll
        for (int j = 1; j < 8; ++j) {
            const float4 v = sm[j][threadIdx.x];
            tot.x += v.x; tot.y += v.y; tot.z += v.z; tot.w += v.w;
        }
        reinterpret_cast<float4*>(g_part + b * L_)[threadIdx.x] = tot;
    }
}

// ---------------------------------------------------------------------------
// softmax for one chunk: HN blocks x 64 threads.
// ---------------------------------------------------------------------------
__global__ __launch_bounds__(64) void k_softmax_h(int chunk) {
    const int n = chunk * HN + blockIdx.x;
    const int l = threadIdx.x;
    const int w = l >> 5;
    const int lane = l & 31;

    float s = 0.f;
    const float* __restrict__ p = g_part + (size_t)n * T_ * L_ + l;
    #pragma unroll
    for (int t = 0; t < T_; ++t) s += p[(size_t)t * L_];

    float m = s;
    #pragma unroll
    for (int off = 16; off; off >>= 1)
        m = fmaxf(m, __shfl_xor_sync(0xffffffffu, m, off));
    __shared__ float wm[2];
    if (lane == 0) wm[w] = m;
    __syncthreads();
    m = fmaxf(wm[0], wm[1]);

    const float e = __expf(s - m);
    float sum = e;
    #pragma unroll
    for (int off = 16; off; off >>= 1)
        sum += __shfl_xor_sync(0xffffffffu, sum, off);
    __shared__ float ws[2];
    if (lane == 0) ws[w] = sum;
    __syncthreads();

    g_probs[n * L_ + l] = e / (ws[0] + ws[1]);
}

// ---------------------------------------------------------------------------
// out for one chunk: 1024 blocks, reversed within the chunk (tail of the
// chunk is the most recently streamed -> hit L2 stack-order). R6 body.
// ---------------------------------------------------------------------------
__global__ __launch_bounds__(256) void k_out_h(const float* __restrict__ q,
                                               float* __restrict__ out,
                                               int chunk) {
    const int local = (HB - 1) - blockIdx.x;      // reversed within chunk
    const int n = chunk * HN + (local >> 6);
    const int t = local & 63;
    const size_t b = (size_t)n * T_ + t;
    const int w = threadIdx.x >> 5;
    const int lane = threadIdx.x & 31;
    const int half = lane >> 4;
    const int l4 = lane & 15;

    const float4 pv = reinterpret_cast<const float4*>(g_probs + n * L_)[l4];
    const float4* __restrict__ qb = reinterpret_cast<const float4*>(q);
    const size_t rowbase = b * C_;
    float* __restrict__ ob = out + ((size_t)t * N_ + n) * C_;

    #pragma unroll 8
    for (int i = 0; i < 16; ++i) {
        const int c = (w << 5) + (i << 1) + half;
        const float4 qv = qb[(rowbase + c) * 16 + l4];
        float v = fmaf(qv.x, pv.x, fmaf(qv.y, pv.y, fmaf(qv.z, pv.z, qv.w * pv.w)));
        #pragma unroll
        for (int off = 8; off; off >>= 1)
            v += __shfl_xor_sync(0xffffffffu, v, off);
        if (l4 == 0) ob[c] = v;
    }
}

// ---------------------------------------------------------------------------
// Host: 2-chunk fork/join pipeline (graph-capturable, same machinery as R8
// but with saturating 1024-block phases).
//   main stream: scores0, softmax0, scores1, softmax1
//   sD:          out0 (∥ scores1), out1
// ---------------------------------------------------------------------------
static cudaStream_t sD = 0;
static cudaEvent_t evF = 0, ev0 = 0, ev1 = 0, evJ = 0;
static int g_inited = 0;

extern "C" void kernel_launch(void* const* d_in, const int* in_sizes, int n_in,
                              void* d_out, int out_size) {
    const float* q   = (const float*)d_in[0];
    const float* key = (const float*)d_in[1];
    float* out = (float*)d_out;

    if (!g_inited) {
        cudaStreamCreateWithFlags(&sD, cudaStreamNonBlocking);
        cudaEventCreateWithFlags(&evF, cudaEventDisableTiming);
        cudaEventCreateWithFlags(&ev0, cudaEventDisableTiming);
        cudaEventCreateWithFlags(&ev1, cudaEventDisableTiming);
        cudaEventCreateWithFlags(&evJ, cudaEventDisableTiming);
        g_inited = 1;
    }

    // fork sD off the main (capture) stream
    cudaEventRecord(evF, 0);
    cudaStreamWaitEvent(sD, evF, 0);

    // chunk 0: scores + softmax on main stream
    k_scores_h<<<HB, 256>>>(q, key, 0);
    k_softmax_h<<<HN, 64>>>(0);
    cudaEventRecord(ev0, 0);

    // chunk 1 scores on main stream (overlaps out0 on sD)
    k_scores_h<<<HB, 256>>>(q, key, 1);
    k_softmax_h<<<HN, 64>>>(1);
    cudaEventRecord(ev1, 0);

    // out chunks on sD, each gated on its softmax
    cudaStreamWaitEvent(sD, ev0, 0);
    k_out_h<<<HB, 256, 0, sD>>>(q, out, 0);
    cudaStreamWaitEvent(sD, ev1, 0);
    k_out_h<<<HB, 256, 0, sD>>>(q, out, 1);

    // join back into the main stream
    cudaEventRecord(evJ, sD);
    cudaStreamWaitEvent(0, evJ, 0);
}

// round 11
// speedup vs baseline: 1.1675x; 1.1437x over previous
#include <cuda_runtime.h>
#include <cuda_bf16.h>
#include <cstdint>

// Shapes: query (N,T,C,L)=(32,64,256,64) fp32; key (T,N,C); out (T,N,C)
#define N_ 32
#define T_ 64
#define C_ 256
#define L_ 64
#define NTILES (N_ * T_)            // 2048 (n,t) tiles of 64KB
#define TILE_F4 (C_ * L_ / 4)       // 4096 float4 per tile

__device__ float    g_part[NTILES * L_];   // per-tile partial scores
__device__ unsigned g_bar;                 // monotonic grid barrier counter

// ---------------------------------------------------------------------------
// Persistent kernel: 512 threads (16 warps), ~3 blocks/SM, all co-resident
// (grid sized via occupancy API). One grid barrier between scores and out.
//   phase 1: scores for tiles [start..last]; LAST tile staged to smem.
//   barrier (monotonic counter -> safe across graph replays, no reset).
//   phase 2: softmax for this block's <=2 n values, redundant per block.
//   phase 3: out pass in reverse; last tile served from smem, rest from L2.
// ---------------------------------------------------------------------------
__global__ __launch_bounds__(512, 3) void k_persist(const float* __restrict__ q,
                                                    const float* __restrict__ key,
                                                    float* __restrict__ out) {
    extern __shared__ float qs[];            // 16384 floats = one tile (64KB)
    __shared__ float4 red[16][16];
    __shared__ float  probs[2][L_];
    __shared__ float  scr[2][2], scr2[2][2];

    const int G    = gridDim.x;
    const int base = NTILES / G;
    const int rem  = NTILES % G;
    const int cnt  = base + (blockIdx.x < rem ? 1 : 0);
    const int start = blockIdx.x * base + min(blockIdx.x, rem);
    const int last  = start + cnt - 1;

    const int tid  = threadIdx.x;
    const int w    = tid >> 5;
    const int lane = tid & 31;
    const int half = lane >> 4;
    const int l4   = lane & 15;
    const int r0   = w << 4;                 // 16 c-rows per warp

    const float4* __restrict__ q4 = reinterpret_cast<const float4*>(q);

    // ================= phase 1: scores =================
    for (int i = start; i <= last; ++i) {
        const int n = i >> 6, t = i & 63;
        // 16 key values per warp, lanes 0-15 hold them (16-31 duplicate)
        const float kreg = key[((size_t)t * N_ + n) * C_ + r0 + l4];

        float4 acc = make_float4(0.f, 0.f, 0.f, 0.f);
        if (i == last) {
            // stage tile to smem (kept for phase 3), compute from smem
            {
                const float4* src = q4 + (size_t)i * TILE_F4;
                const unsigned sb = (unsigned)__cvta_generic_to_shared(qs);
                #pragma unroll
                for (int k2 = 0; k2 < 8; ++k2) {
                    const int idx = tid + (k2 << 9);
                    asm volatile("cp.async.cg.shared.global [%0], [%1], 16;\n"
                                 :: "r"(sb + idx * 16), "l"(src + idx));
                }
                asm volatile("cp.async.commit_group;\n");
                asm volatile("cp.async.wait_group 0;\n");
            }
            __syncthreads();
            const float4* qs4 = reinterpret_cast<const float4*>(qs);
            #pragma unroll
            for (int j = 0; j < 8; ++j) {
                const int row = (j << 1) + half;
                const float kv = __shfl_sync(0xffffffffu, kreg, row);
                const float4 qv = qs4[(r0 + row) * 16 + l4];
                acc.x = fmaf(kv, qv.x, acc.x);
                acc.y = fmaf(kv, qv.y, acc.y);
                acc.z = fmaf(kv, qv.z, acc.z);
                acc.w = fmaf(kv, qv.w, acc.w);
            }
        } else {
            #pragma unroll
            for (int j = 0; j < 8; ++j) {
                const int row = (j << 1) + half;
                const float kv = __shfl_sync(0xffffffffu, kreg, row);
                const float4 qv = q4[((size_t)i * C_ + r0 + row) * 16 + l4];
                acc.x = fmaf(kv, qv.x, acc.x);
                acc.y = fmaf(kv, qv.y, acc.y);
                acc.z = fmaf(kv, qv.z, acc.z);
                acc.w = fmaf(kv, qv.w, acc.w);
            }
        }
        // combine row pair halves, then cross-warp reduce
        acc.x += __shfl_xor_sync(0xffffffffu, acc.x, 16);
        acc.y += __shfl_xor_sync(0xffffffffu, acc.y, 16);
        acc.z += __shfl_xor_sync(0xffffffffu, acc.z, 16);
        acc.w += __shfl_xor_sync(0xffffffffu, acc.w, 16);
        if (half == 0) red[w][l4] = acc;
        __syncthreads();
        if (tid < 16) {
            float4 tot = red[0][tid];
            #pragma unroll
            for (int j = 1; j < 16; ++j) {
                const float4 v = red[j][tid];
                tot.x += v.x; tot.y += v.y; tot.z += v.z; tot.w += v.w;
            }
            reinterpret_cast<float4*>(g_part + (size_t)i * L_)[tid] = tot;
        }
        __syncthreads();
    }

    // ================= grid barrier (monotonic, replay-safe) =================
    __threadfence();
    if (tid == 0) {
        const unsigned old = atomicAdd(&g_bar, 1u);
        const unsigned target = (old / (unsigned)G + 1u) * (unsigned)G;
        while (atomicAdd(&g_bar, 0u) < target) __nanosleep(64);
    }
    __syncthreads();
    __threadfence();

    // ================= phase 2: softmax for this block's n values ===========
    const int n0 = start >> 6, n1 = last >> 6;  // contiguous range spans <=2 n
    const int grp = (tid < 64) ? 0
                  : ((tid >= 256 && tid < 320 && n1 != n0) ? 1 : -1);
    const int gl = tid & 63;
    const int gw = (tid >> 5) & 1;
    float s = 0.f, e = 0.f;
    if (grp >= 0) {
        const int nn = (grp == 1) ? n1 : n0;
        const float* __restrict__ p = g_part + (size_t)nn * T_ * L_ + gl;
        #pragma unroll
        for (int t2 = 0; t2 < T_; ++t2) s += p[t2 * L_];
        float m = s;
        #pragma unroll
        for (int off = 16; off; off >>= 1)
            m = fmaxf(m, __shfl_xor_sync(0xffffffffu, m, off));
        if (lane == 0) scr[grp][gw] = m;
    }
    __syncthreads();
    if (grp >= 0) {
        const float m = fmaxf(scr[grp][0], scr[grp][1]);
        e = __expf(s - m);
        float sum = e;
        #pragma unroll
        for (int off = 16; off; off >>= 1)
            sum += __shfl_xor_sync(0xffffffffu, sum, off);
        if (lane == 0) scr2[grp][gw] = sum;
    }
    __syncthreads();
    if (grp >= 0) probs[grp][gl] = e / (scr2[grp][0] + scr2[grp][1]);
    __syncthreads();

    // ================= phase 3: out pass (reverse; last tile from smem) =====
    for (int i = last; i >= start; --i) {
        const int n = i >> 6, t = i & 63;
        const float* __restrict__ pr = probs[(n == n0) ? 0 : 1];
        float* __restrict__ ob = out + ((size_t)t * N_ + n) * C_;

        if (i == last) {
            // smem path: lane holds l-pair, full-warp reduce, 16 rows/warp
            const float2 pp = reinterpret_cast<const float2*>(pr)[lane];
            const float2* qs2 = reinterpret_cast<const float2*>(qs);
            #pragma unroll
            for (int j = 0; j < 16; ++j) {
                const int row = r0 + j;
                const float2 qv = qs2[row * 32 + lane];
                float v = fmaf(qv.x, pp.x, qv.y * pp.y);
                #pragma unroll
                for (int off = 16; off; off >>= 1)
                    v += __shfl_xor_sync(0xffffffffu, v, off);
                if (lane == 0) ob[row] = v;
            }
        } else {
            // gmem (L2-hot) path: half-warp per row, float4
            const float4 pv = reinterpret_cast<const float4*>(pr)[l4];
            #pragma unroll
            for (int j = 0; j < 8; ++j) {
                const int row = r0 + (j << 1) + half;
                const float4 qv = q4[((size_t)i * C_ + row) * 16 + l4];
                float v = fmaf(qv.x, pv.x,
                          fmaf(qv.y, pv.y,
                          fmaf(qv.z, pv.z, qv.w * pv.w)));
                #pragma unroll
                for (int off = 8; off; off >>= 1)
                    v += __shfl_xor_sync(0xffffffffu, v, off);
                if (l4 == 0) ob[row] = v;
            }
        }
    }
}

// ---------------------------------------------------------------------------
// Host: grid sized to guaranteed co-residency via occupancy API (first call,
// outside capture). Single launch per call -> trivially graph-capturable.
// ---------------------------------------------------------------------------
static int g_grid = 0;

extern "C" void kernel_launch(void* const* d_in, const int* in_sizes, int n_in,
                              void* d_out, int out_size) {
    const float* q   = (const float*)d_in[0];
    const float* key = (const float*)d_in[1];
    float* out = (float*)d_out;

    if (!g_grid) {
        cudaFuncSetAttribute(k_persist, cudaFuncAttributeMaxDynamicSharedMemorySize,
                             65536);
        int dev = 0, sms = 0, nb = 0;
        cudaGetDevice(&dev);
        cudaDeviceGetAttribute(&sms, cudaDevAttrMultiProcessorCount, dev);
        cudaOccupancyMaxActiveBlocksPerMultiprocessor(&nb, k_persist, 512, 65536);
        if (nb < 1) nb = 1;
        if (nb > 3) nb = 3;
        g_grid = sms * nb;
        if (g_grid > NTILES) g_grid = NTILES;
    }

    k_persist<<<g_grid, 512, 65536>>>(q, key, out);
}

// round 12
// speedup vs baseline: 1.5813x; 1.3545x over previous
#include <cuda_runtime.h>
#include <cuda_bf16.h>

// Shapes: query (N,T,C,L)=(32,64,256,64) fp32; key (T,N,C); out (T,N,C)
#define N_ 32
#define T_ 64
#define C_ 256
#define L_ 64
#define P_THRESH 1e-7f

__device__ float g_part[N_ * T_ * L_];   // per-(n,t) partial scores
__device__ float g_w[N_][L_];            // compact softmax weights
__device__ int   g_idx[N_][L_];          // compact l indices
__device__ int   g_cnt[N_];              // list length per n

// ---------------------------------------------------------------------------
// Kernel 1: partial scores (unchanged proven R6 body, 24.1us @ 73% DRAM).
// ---------------------------------------------------------------------------
__global__ __launch_bounds__(256, 6) void k_scores(const float* __restrict__ q,
                                                   const float* __restrict__ key) {
    const int b = blockIdx.x;
    const int n = b >> 6;
    const int t = b & 63;
    const int w = threadIdx.x >> 5;
    const int lane = threadIdx.x & 31;
    const int half = lane >> 4;
    const int l4 = lane & 15;

    const float kreg = key[((size_t)t * N_ + n) * C_ + (w << 5) + lane];
    const float4* __restrict__ qb = reinterpret_cast<const float4*>(q);
    const size_t rowbase = (size_t)b * C_;

    float4 acc = make_float4(0.f, 0.f, 0.f, 0.f);
    #pragma unroll
    for (int i = 0; i < 16; ++i) {
        const int r = (i << 1) + half;
        const float kv = __shfl_sync(0xffffffffu, kreg, r);
        const float4 qv = qb[(rowbase + (w << 5) + r) * 16 + l4];
        acc.x = fmaf(kv, qv.x, acc.x);
        acc.y = fmaf(kv, qv.y, acc.y);
        acc.z = fmaf(kv, qv.z, acc.z);
        acc.w = fmaf(kv, qv.w, acc.w);
    }
    acc.x += __shfl_xor_sync(0xffffffffu, acc.x, 16);
    acc.y += __shfl_xor_sync(0xffffffffu, acc.y, 16);
    acc.z += __shfl_xor_sync(0xffffffffu, acc.z, 16);
    acc.w += __shfl_xor_sync(0xffffffffu, acc.w, 16);

    __shared__ float4 sm[8][16];
    if (half == 0) sm[w][l4] = acc;
    __syncthreads();
    if (threadIdx.x < 16) {
        float4 tot = sm[0][threadIdx.x];
        #pragma unroll
        for (int j = 1; j < 8; ++j) {
            const float4 v = sm[j][threadIdx.x];
            tot.x += v.x; tot.y += v.y; tot.z += v.z; tot.w += v.w;
        }
        reinterpret_cast<float4*>(g_part + (size_t)b * L_)[threadIdx.x] = tot;
    }
}

// ---------------------------------------------------------------------------
// Kernel 2: reduce over t + stable softmax + COMPACTION of significant
// weights (p > P_THRESH) into a deterministic-order list per n.
// 32 blocks x 64 threads (thread tid == l).
// ---------------------------------------------------------------------------
__global__ __launch_bounds__(64) void k_softmax() {
    const int n = blockIdx.x;
    const int l = threadIdx.x;
    const int w = l >> 5;
    const int lane = l & 31;

    float s = 0.f;
    const float* __restrict__ p = g_part + (size_t)n * T_ * L_ + l;
    #pragma unroll
    for (int t = 0; t < T_; ++t) s += p[(size_t)t * L_];

    float m = s;
    #pragma unroll
    for (int off = 16; off; off >>= 1)
        m = fmaxf(m, __shfl_xor_sync(0xffffffffu, m, off));
    __shared__ float wm[2];
    if (lane == 0) wm[w] = m;
    __syncthreads();
    m = fmaxf(wm[0], wm[1]);

    const float e = __expf(s - m);
    float sum = e;
    #pragma unroll
    for (int off = 16; off; off >>= 1)
        sum += __shfl_xor_sync(0xffffffffu, sum, off);
    __shared__ float ws[2];
    if (lane == 0) ws[w] = sum;
    __syncthreads();
    const float prob = e / (ws[0] + ws[1]);

    // ---- compact significant weights, deterministic l-order ----
    const bool keep = prob > P_THRESH;
    const unsigned mask = __ballot_sync(0xffffffffu, keep);
    const int prefix = __popc(mask & ((1u << lane) - 1u));
    __shared__ int wcnt[2];
    if (lane == 0) wcnt[w] = __popc(mask);
    __syncthreads();
    const int base = (w == 1) ? wcnt[0] : 0;
    if (keep) {
        g_w[n][base + prefix] = prob;
        g_idx[n][base + prefix] = l;
    }
    if (l == 0) g_cnt[n] = wcnt[0] + wcnt[1];
}

// ---------------------------------------------------------------------------
// Kernel 3: sparse gather. out[t,n,c] = sum_{j<cnt[n]} w[n][j]*q[n,t,c,idx[n][j]]
// One block per (n,t), thread tid == c. Typically cnt==1 -> one 4B load per
// thread (~16MB of 32B sectors total vs 128MB dense). Exhaustive above
// threshold -> correct for any input data.
// ---------------------------------------------------------------------------
__global__ __launch_bounds__(256) void k_gather(const float* __restrict__ q,
                                                float* __restrict__ out) {
    const int b = blockIdx.x;
    const int n = b >> 6;
    const int t = b & 63;
    const int c = threadIdx.x;

    const int m = g_cnt[n];
    const float* __restrict__ qrow = q + ((size_t)b * C_ + c) * L_;

    float acc = 0.f;
    for (int j = 0; j < m; ++j)
        acc = fmaf(g_w[n][j], __ldg(qrow + g_idx[n][j]), acc);

    out[((size_t)t * N_ + n) * C_ + c] = acc;
}

extern "C" void kernel_launch(void* const* d_in, const int* in_sizes, int n_in,
                              void* d_out, int out_size) {
    const float* q   = (const float*)d_in[0];
    const float* key = (const float*)d_in[1];
    float* out = (float*)d_out;

    k_scores<<<N_ * T_, 256>>>(q, key);
    k_softmax<<<N_, 64>>>();
    k_gather<<<N_ * T_, 256>>>(q, out);
}

// round 13
// speedup vs baseline: 1.6558x; 1.0471x over previous
#include <cuda_runtime.h>
#include <cuda_bf16.h>

// Shapes: query (N,T,C,L)=(32,64,256,64) fp32; key (T,N,C); out (T,N,C)
#define N_ 32
#define T_ 64
#define C_ 256
#define L_ 64
#define P_THRESH 1e-7f

__device__ float g_part[N_ * T_ * L_];   // per-(n,t) partial scores

// ---------------------------------------------------------------------------
// Kernel 1: partial scores (unchanged proven body, 24.4us @ 72.5% DRAM).
// ---------------------------------------------------------------------------
__global__ __launch_bounds__(256, 6) void k_scores(const float* __restrict__ q,
                                                   const float* __restrict__ key) {
    const int b = blockIdx.x;
    const int n = b >> 6;
    const int t = b & 63;
    const int w = threadIdx.x >> 5;
    const int lane = threadIdx.x & 31;
    const int half = lane >> 4;
    const int l4 = lane & 15;

    const float kreg = key[((size_t)t * N_ + n) * C_ + (w << 5) + lane];
    const float4* __restrict__ qb = reinterpret_cast<const float4*>(q);
    const size_t rowbase = (size_t)b * C_;

    float4 acc = make_float4(0.f, 0.f, 0.f, 0.f);
    #pragma unroll
    for (int i = 0; i < 16; ++i) {
        const int r = (i << 1) + half;
        const float kv = __shfl_sync(0xffffffffu, kreg, r);
        const float4 qv = qb[(rowbase + (w << 5) + r) * 16 + l4];
        acc.x = fmaf(kv, qv.x, acc.x);
        acc.y = fmaf(kv, qv.y, acc.y);
        acc.z = fmaf(kv, qv.z, acc.z);
        acc.w = fmaf(kv, qv.w, acc.w);
    }
    acc.x += __shfl_xor_sync(0xffffffffu, acc.x, 16);
    acc.y += __shfl_xor_sync(0xffffffffu, acc.y, 16);
    acc.z += __shfl_xor_sync(0xffffffffu, acc.z, 16);
    acc.w += __shfl_xor_sync(0xffffffffu, acc.w, 16);

    __shared__ float4 sm[8][16];
    if (half == 0) sm[w][l4] = acc;
    __syncthreads();
    if (threadIdx.x < 16) {
        float4 tot = sm[0][threadIdx.x];
        #pragma unroll
        for (int j = 1; j < 8; ++j) {
            const float4 v = sm[j][threadIdx.x];
            tot.x += v.x; tot.y += v.y; tot.z += v.z; tot.w += v.w;
        }
        reinterpret_cast<float4*>(g_part + (size_t)b * L_)[threadIdx.x] = tot;
    }
}

// ---------------------------------------------------------------------------
// Kernel 2 (fused): per-(n,t) block recomputes its n's softmax redundantly
// from g_part (16KB, L2-hot: 64 blocks share it), compacts significant
// weights in smem, then does the sparse gather. 2 launches total.
// ---------------------------------------------------------------------------
__global__ __launch_bounds__(256) void k_sg(const float* __restrict__ q,
                                            float* __restrict__ out) {
    const int b = blockIdx.x;
    const int n = b >> 6;
    const int t = b & 63;
    const int tid = threadIdx.x;
    const int lane = tid & 31;

    __shared__ float s_part[4][L_];
    __shared__ float s_w[L_];
    __shared__ int   s_idx[L_];
    __shared__ int   s_cnt;
    __shared__ float s_red[4];

    // ---- phase 1: sum partials over t, 4-way split, coalesced over l ----
    {
        const int l = tid & 63;
        const int tp = tid >> 6;               // 4 groups x 16 t's
        float s = 0.f;
        const float* __restrict__ p =
            g_part + ((size_t)n * T_ + tp * 16) * L_ + l;
        #pragma unroll
        for (int tt = 0; tt < 16; ++tt) s += p[tt * L_];
        s_part[tp][l] = s;
    }
    __syncthreads();

    // ---- phase 2: softmax + compaction (threads 0..63) ----
    if (tid < L_) {
        const int w2 = tid >> 5;
        float s = s_part[0][tid] + s_part[1][tid]
                + s_part[2][tid] + s_part[3][tid];

        float m = s;
        #pragma unroll
        for (int off = 16; off; off >>= 1)
            m = fmaxf(m, __shfl_xor_sync(0xffffffffu, m, off));
        if (lane == 0) s_red[w2] = m;
        __syncwarp();
        // cross-warp max via smem (both warps write before read: use bar)
        __syncthreads();
        m = fmaxf(s_red[0], s_red[1]);

        const float e = __expf(s - m);
        float sum = e;
        #pragma unroll
        for (int off = 16; off; off >>= 1)
            sum += __shfl_xor_sync(0xffffffffu, sum, off);
        if (lane == 0) s_red[2 + w2] = sum;
        __syncthreads();
        const float prob = e / (s_red[2] + s_red[3]);

        // deterministic compaction of significant weights
        const bool keep = prob > P_THRESH;
        const unsigned mask = __ballot_sync(0xffffffffu, keep);
        const int prefix = __popc(mask & ((1u << lane) - 1u));
        __shared__ int wcnt[2];
        if (lane == 0) wcnt[w2] = __popc(mask);
        __syncthreads();
        const int base = (w2 == 1) ? wcnt[0] : 0;
        if (keep) {
            s_w[base + prefix] = prob;
            s_idx[base + prefix] = tid;
        }
        if (tid == 0) s_cnt = wcnt[0] + wcnt[1];
    } else {
        __syncthreads();   // match phase-2 barriers
        __syncthreads();
        __syncthreads();
    }
    __syncthreads();

    // ---- phase 3: sparse gather (thread tid == c) ----
    const int cnt = s_cnt;
    const float* __restrict__ qrow = q + ((size_t)b * C_ + tid) * L_;
    float acc = 0.f;
    for (int j = 0; j < cnt; ++j)
        acc = fmaf(s_w[j], __ldg(qrow + s_idx[j]), acc);

    out[((size_t)t * N_ + n) * C_ + tid] = acc;
}

extern "C" void kernel_launch(void* const* d_in, const int* in_sizes, int n_in,
                              void* d_out, int out_size) {
    const float* q   = (const float*)d_in[0];
    const float* key = (const float*)d_in[1];
    float* out = (float*)d_out;

    k_scores<<<N_ * T_, 256>>>(q, key);
    k_sg<<<N_ * T_, 256>>>(q, out);
}